// round 16
// baseline (speedup 1.0000x reference)
#include <cuda_runtime.h>
#include <math.h>

#define NB 64
#define HH 30
#define WW 60
#define DD 64
#define ROWB (WW*DD*4)      // 15360 bytes per (b,h) image row

// ---------------- scratch (device globals; no allocation) ----------------
__device__ float g_part[NB*16*16*DD];     // balanced partial cell sums (4 MB)
__device__ float g_dvec[NB*8*16*DD];      // dvec per (batch,hseg,combo) (2 MB)
__device__ float g_s[NB*128];             // raw s
__device__ unsigned g_cntA[NB*32];        // barrier counters (monotonic, replay-safe)
__device__ unsigned g_cntB[NB*32];

// ---------------- geometry LUTs ----------------
__constant__ int c_wstart[16] = {0,6,10,12,15,18,20,24,30,36,40,42,45,48,50,54};
__constant__ int c_wlen[16]   = {6,4,2,3,3,2,4,6, 6,4,2,3,3,2,4,6};
__constant__ unsigned char c_hseg[30] = {
  0,0,0,0,0,0, 1,1,1,1, 2,2, 3,3,3, 4,4,4, 5,5, 6,6,6,6, 7,7,7,7,7,7};
__constant__ unsigned char c_wseg[60] = {
  0,0,0,0,0,0, 1,1,1,1, 2,2, 3,3,3, 4,4,4, 5,5, 6,6,6,6, 7,7,7,7,7,7,
  8,8,8,8,8,8, 9,9,9,9, 10,10, 11,11,11, 12,12,12, 13,13, 14,14,14,14,
  15,15,15,15,15,15};
__constant__ unsigned char c_rh0[8]  = {0,1,1,2,2,3,3,4};
__constant__ unsigned char c_rh1[8]  = {0,0,1,1,1,1,2,2};
__constant__ unsigned char c_rh2[8]  = {0,0,0,0,1,1,1,1};
__constant__ unsigned char c_rw0[16] = {0,1,1,2,2,3,3,4,5,6,6,7,7,8,8,9};
__constant__ unsigned char c_rw1[16] = {0,0,1,1,1,1,2,2,3,3,4,4,4,4,5,5};
__constant__ unsigned char c_rw2[16] = {0,0,0,0,1,1,1,1,2,2,2,2,3,3,3,3};
__constant__ unsigned char p0_hf[5]={0,1,3,5,7},              p0_hc[5]={1,2,2,2,1};
__constant__ unsigned char p0_wf[10]={0,1,3,5,7,8,9,11,13,15},p0_wc[10]={1,2,2,2,1,1,2,2,2,1};
__constant__ unsigned char p1_hf[3]={0,2,6},                  p1_hc[3]={2,4,2};
__constant__ unsigned char p1_wf[6]={0,2,6,8,10,14},          p1_wc[6]={2,4,2,2,4,2};
__constant__ unsigned char p2_hf[2]={0,4},                    p2_hc[2]={4,4};
__constant__ unsigned char p2_wf[4]={0,4,8,12},               p2_wc[4]={4,4,4,4};
// hseg -> two g_part slots summing to its cells (slots 1,9,15 are zeros)
__constant__ unsigned char c_i1[8] = {0,3,5,7,8,10,11,13};
__constant__ unsigned char c_i2[8] = {2,4,6,1,9,15,12,14};

// ---------------- async / barrier helpers ----------------
__device__ __forceinline__ unsigned s2u(const void* p) {
    unsigned a;
    asm("{ .reg .u64 t; cvta.to.shared.u64 t, %1; cvt.u32.u64 %0, t; }"
        : "=r"(a) : "l"(p));
    return a;
}
__device__ __forceinline__ void mbar_init(unsigned m, unsigned cnt) {
    asm volatile("mbarrier.init.shared.b64 [%0], %1;" :: "r"(m), "r"(cnt) : "memory");
}
__device__ __forceinline__ void mbar_expect(unsigned m, unsigned bytes) {
    asm volatile("mbarrier.arrive.expect_tx.shared.b64 _, [%0], %1;"
                 :: "r"(m), "r"(bytes) : "memory");
}
__device__ __forceinline__ void bulk_g2s(unsigned dst, const void* src,
                                         unsigned bytes, unsigned m) {
    asm volatile(
        "cp.async.bulk.shared::cluster.global.mbarrier::complete_tx::bytes "
        "[%0], [%1], %2, [%3];"
        :: "r"(dst), "l"(src), "r"(bytes), "r"(m) : "memory");
}
__device__ __forceinline__ void mbar_wait(unsigned m, unsigned parity) {
    asm volatile(
        "{\n\t.reg .pred P;\n\t"
        "WL_%=:\n\t"
        "mbarrier.try_wait.parity.acquire.cta.shared::cta.b64 P, [%0], %1;\n\t"
        "@P bra WD_%=;\n\t"
        "bra WL_%=;\n\t"
        "WD_%=:\n\t}"
        :: "r"(m), "r"(parity) : "memory");
}
__device__ __forceinline__ void fence_async() {
    asm volatile("fence.proxy.async.shared::cta;" ::: "memory");
}
__device__ __forceinline__ void batch_barrier(unsigned* cnt, int tid) {
    __threadfence();                         // release this block's stores
    __syncthreads();
    if (tid == 0) {
        unsigned o = atomicAdd(cnt, 1u);
        unsigned target = ((o >> 3) + 1u) << 3;   // next multiple of 8
        while ((int)(*(volatile unsigned*)cnt - target) < 0) __nanosleep(128);
        __threadfence();                     // acquire
    }
    __syncthreads();
}

// ============ fused kernel: grid = 512 = (batch, k), one wave ============
__global__ __launch_bounds__(256, 4) void k_fused(
    const float* __restrict__ x,
    const float* __restrict__ qk_w,
    const float* __restrict__ qk_b,
    const float* __restrict__ score_w,
    const float* __restrict__ score_b,
    const float* __restrict__ noise_x,
    const float* __restrict__ noise_r,
    float* __restrict__ out)
{
    // arena layout (byte offsets):
    //  A: slabs 0/1/2 at 0/15360/30720                        (46080)
    //  B: cells @0 (32768), rs4 @32768 (5120), ush4 @37888 (4096),
    //     tsm @41984 (4096); after u: Wk^T pad-65 @0 (16640), Wq @16640 (16384)
    //  C: dshA @0, dshB @4096, ash @8192, bshA/B @9216
    __shared__ __align__(128) unsigned char arena[46080];
    __shared__ __align__(8) unsigned long long mbar[3];
    __shared__ float qkb[128];

    int bi  = blockIdx.x;
    int b   = bi >> 3, k = bi & 7;
    int tid = threadIdx.x;
    int start = (k*30) >> 3, end = ((k+1)*30) >> 3;   // sizes 3,4,4,4,3,4,4,4
    int rows  = end - start;
    int hsA = c_hseg[start], hsB = c_hseg[end - 1];   // range spans <= 2 hsegs

    unsigned mb = s2u(mbar);
    if (tid == 0)
        for (int i = 0; i < 3; i++) mbar_init(mb + i*8, 1);
    if (tid < 128) qkb[tid] = qk_b[tid];
    float w0 = score_w[0], w1 = score_w[1], w2 = score_w[2];
    float sb = score_b[0];
    // noise preload (input-only): overlaps all phases
    int gi0 = (b*HH + start)*WW;
    float nxv = 0.f, nrv = 0.f;
    if (tid < rows*WW) { nxv = noise_x[gi0 + tid]; nrv = noise_r[gi0 + tid]; }
    __syncthreads();

    const char* xrow = (const char*)x + (size_t)(b*HH + start) * ROWB;

    // ---------------- phase A: balanced TMA cell partials -------------------
    {
        if (tid == 0) {
            int pre = rows < 3 ? rows : 3;
            for (int r = 0; r < pre; r++) {
                mbar_expect(mb + r*8, ROWB);
                bulk_g2s(s2u(arena + r*15360), xrow + (size_t)r*ROWB, ROWB, mb + r*8);
            }
        }
        int ws = tid >> 4, j = tid & 15;
        int a0i = c_wstart[ws], l0 = c_wlen[ws];
        float4 accA = make_float4(0.f,0.f,0.f,0.f);
        float4 accB = make_float4(0.f,0.f,0.f,0.f);
        #pragma unroll
        for (int r = 0; r < 4; r++) {
            if (r < rows) {
                int s = r % 3;
                mbar_wait(mb + s*8, r/3);
                const float4* sl = (const float4*)(arena + s*15360) + a0i*16 + j;
                float4 t = make_float4(0.f,0.f,0.f,0.f);
                #pragma unroll
                for (int w = 0; w < 6; w++) {
                    if (w < l0) {
                        float4 v = sl[w*16];
                        t.x += v.x; t.y += v.y; t.z += v.z; t.w += v.w;
                    }
                }
                if ((int)c_hseg[start + r] == hsA) {
                    accA.x += t.x; accA.y += t.y; accA.z += t.z; accA.w += t.w;
                } else {
                    accB.x += t.x; accB.y += t.y; accB.z += t.z; accB.w += t.w;
                }
                if (r + 3 < rows) {          // only rows=4, r=0: re-arm slab 0
                    __syncthreads();
                    if (tid == 0) {
                        fence_async();
                        mbar_expect(mb + s*8, ROWB);
                        bulk_g2s(s2u(arena + s*15360), xrow + (size_t)(r+3)*ROWB,
                                 ROWB, mb + s*8);
                    }
                }
            }
        }
        float4* pp = (float4*)(g_part + ((size_t)b*16 + k*2) * 1024);
        pp[ws*16 + j]       = accA;          // slot k*2
        pp[256 + ws*16 + j] = accB;          // slot k*2+1 (zeros if single-hseg)
    }

    batch_barrier(&g_cntA[b*32], tid);

    // ---------------- phase B: dense cell merge -> smem regions -> dvec -----
    {
        float4* cells4 = (float4*)arena;                 // 8 hsegs x 256 f4
        float4* rs4    = (float4*)(arena + 32768);       // 20 regions x 16 f4
        float4* ush4   = (float4*)(arena + 37888);       // 16 combos x 16 f4
        float*  tsm    = (float*)(arena + 41984);        // 16 x 64
        float*  Mkt    = (float*)arena;                  // Wk^T pad-65 (post-u)
        float*  Wqs    = (float*)(arena + 16640);        // Wq straight (post-u)

        // 1) dense cooperative merge of partial slots (independent L2 loads)
        const float4* pb4 = (const float4*)(g_part + (size_t)b * 16384);
        #pragma unroll
        for (int it = 0; it < 8; it++) {
            int v = tid + it*256;                        // 0..2047
            int hs2 = v >> 8, o = v & 255;
            float4 v1 = pb4[(int)c_i1[hs2]*256 + o];
            float4 v2 = pb4[(int)c_i2[hs2]*256 + o];
            cells4[v] = make_float4(v1.x+v2.x, v1.y+v2.y, v1.z+v2.z, v1.w+v2.w);
        }
        __syncthreads();

        // 2) region sums from smem (LDS gather, short chains)
        int rh0 = c_rh0[k], rh1 = c_rh1[k], rh2 = c_rh2[k];
        for (int v = tid; v < 320; v += 256) {
            int jj = v >> 4, dq = v & 15;
            int hf, hc, wf, wc;
            if (jj < 10)      { hf=p0_hf[rh0]; hc=p0_hc[rh0]; wf=p0_wf[jj];   wc=p0_wc[jj]; }
            else if (jj < 16) { int rw=jj-10; hf=p1_hf[rh1]; hc=p1_hc[rh1]; wf=p1_wf[rw]; wc=p1_wc[rw]; }
            else              { int rw=jj-16; hf=p2_hf[rh2]; hc=p2_hc[rh2]; wf=p2_wf[rw]; wc=p2_wc[rw]; }
            float4 s = make_float4(0.f,0.f,0.f,0.f);
            for (int a = 0; a < hc; a++) {
                const float4* cr = cells4 + ((hf + a)*16 + wf)*16 + dq;
                for (int c2 = 0; c2 < wc; c2++) {
                    float4 v1 = cr[c2*16];
                    s.x += v1.x; s.y += v1.y; s.z += v1.z; s.w += v1.w;
                }
            }
            rs4[v] = s;
        }
        __syncthreads();

        float aw0 = w0*(1.f/36.f), aw1 = w1*(1.f/100.f), aw2 = w2*(1.f/225.f);
        float wsum = w0 + w1 + w2;

        // 3) u[combo] (256 threads = 16 combos x 16 quads)
        {
            int wsg = tid >> 4, dq = tid & 15;
            float4 r0 = rs4[(int)c_rw0[wsg]*16 + dq];
            float4 r1 = rs4[(10 + (int)c_rw1[wsg])*16 + dq];
            float4 r2 = rs4[(16 + (int)c_rw2[wsg])*16 + dq];
            float4 u;
            u.x = aw0*r0.x + aw1*r1.x + aw2*r2.x;
            u.y = aw0*r0.y + aw1*r1.y + aw2*r2.y;
            u.z = aw0*r0.z + aw1*r1.z + aw2*r2.z;
            u.w = aw0*r0.w + aw1*r1.w + aw2*r2.w;
            ush4[tid] = u;
        }
        __syncthreads();                     // cells + rs dead

        // 4) combined weight fill: Wk^T (pad-65) @0  AND  Wq (straight) @16640
        for (int v = tid; v < 4096; v += 256) {
            int ee = v >> 6, d = v & 63;
            Mkt[d*65 + ee] = qk_w[4096 + v];
        }
        for (int v = tid; v < 4096; v += 256) Wqs[v] = qk_w[v];
        __syncthreads();

        // 5) t[c] = Wk u[c] + wsum*bk   (thread = (e, 4-combo group))
        int e = tid & 63, cg = tid >> 6;
        {
            float init = wsum * qkb[64 + e];
            float t0 = init, t1 = init, t2 = init, t3 = init;
            #pragma unroll
            for (int fq = 0; fq < 16; fq++) {
                int d = fq*4;
                float m0 = Mkt[(d+0)*65 + e];
                float m1 = Mkt[(d+1)*65 + e];
                float m2 = Mkt[(d+2)*65 + e];
                float m3 = Mkt[(d+3)*65 + e];
                float4 ua = ush4[(cg*4 + 0)*16 + fq];
                float4 ub = ush4[(cg*4 + 1)*16 + fq];
                float4 uc = ush4[(cg*4 + 2)*16 + fq];
                float4 ud = ush4[(cg*4 + 3)*16 + fq];
                t0 += m0*ua.x + m1*ua.y + m2*ua.z + m3*ua.w;
                t1 += m0*ub.x + m1*ub.y + m2*ub.z + m3*ub.w;
                t2 += m0*uc.x + m1*uc.y + m2*uc.z + m3*uc.w;
                t3 += m0*ud.x + m1*ud.y + m2*ud.z + m3*ud.w;
            }
            tsm[(cg*4 + 0)*64 + e] = t0;
            tsm[(cg*4 + 1)*64 + e] = t1;
            tsm[(cg*4 + 2)*64 + e] = t2;
            tsm[(cg*4 + 3)*64 + e] = t3;
        }
        __syncthreads();

        // 6) s[c] = bq . t[c]
        int lane = tid & 31, warp = tid >> 5;
        for (int c = warp; c < 16; c += 8) {
            float sv = tsm[c*64 + lane]      * qkb[lane]
                     + tsm[c*64 + 32 + lane] * qkb[32 + lane];
            #pragma unroll
            for (int o = 16; o; o >>= 1) sv += __shfl_xor_sync(0xffffffffu, sv, o);
            if (lane == 0) g_s[b*128 + k*16 + c] = sv;
        }

        // 7) dvec[c] = Wq^T t[c] -> global
        {
            int jj = tid & 63;
            float d0 = 0.f, d1 = 0.f, d2 = 0.f, d3 = 0.f;
            const float4* t0p = (const float4*)(tsm + (cg*4 + 0)*64);
            const float4* t1p = (const float4*)(tsm + (cg*4 + 1)*64);
            const float4* t2p = (const float4*)(tsm + (cg*4 + 2)*64);
            const float4* t3p = (const float4*)(tsm + (cg*4 + 3)*64);
            #pragma unroll
            for (int eq = 0; eq < 16; eq++) {
                int ee = eq*4;
                float a0v = Wqs[(ee+0)*64 + jj];
                float a1v = Wqs[(ee+1)*64 + jj];
                float a2v = Wqs[(ee+2)*64 + jj];
                float a3v = Wqs[(ee+3)*64 + jj];
                float4 ta = t0p[eq], tb = t1p[eq], tc = t2p[eq], td = t3p[eq];
                d0 += a0v*ta.x + a1v*ta.y + a2v*ta.z + a3v*ta.w;
                d1 += a0v*tb.x + a1v*tb.y + a2v*tb.z + a3v*tb.w;
                d2 += a0v*tc.x + a1v*tc.y + a2v*tc.z + a3v*tc.w;
                d3 += a0v*td.x + a1v*td.y + a2v*td.z + a3v*td.w;
            }
            float* dst = g_dvec + ((size_t)(b*8 + k)*16 + cg*4)*64;
            dst[0*64 + jj] = d0;
            dst[1*64 + jj] = d1;
            dst[2*64 + jj] = d2;
            dst[3*64 + jj] = d3;
        }
    }

    batch_barrier(&g_cntB[b*32], tid);

    // ---------------- phase C: direct-L2 dot, explicit ILP ------------------
    {
        float4* dshA4 = (float4*)arena;
        float4* dshB4 = (float4*)(arena + 4096);
        float*  ashp  = (float*)(arena + 8192);          // rows*60 <= 240
        float*  bshA  = (float*)(arena + 9216);
        float*  bshB  = bshA + 16;

        const float4* srcA = (const float4*)(g_dvec + (size_t)(b*8 + hsA)*1024);
        const float4* srcB = (const float4*)(g_dvec + (size_t)(b*8 + hsB)*1024);
        dshA4[tid] = srcA[tid];              // 256 f4 = full 16x64 each
        dshB4[tid] = srcB[tid];
        if (tid < 16) {
            bshA[tid] = 0.125f * g_s[b*128 + hsA*16 + tid] + sb;
            bshB[tid] = 0.125f * g_s[b*128 + hsB*16 + tid] + sb;
        }
        __syncthreads();

        int lane = tid & 31, warp = tid >> 5;
        int half = lane >> 4, jq = lane & 15;
        int p0 = warp*2 + half;              // 0..15
        int p3 = p0 + 48;
        bool v3 = (p3 < WW);
        int ws0 = c_wseg[p0], ws1 = c_wseg[p0+16], ws2 = c_wseg[p0+32];
        int ws3 = v3 ? (int)c_wseg[p3] : 0;
        const float4* xb4 = (const float4*)xrow;   // rows x 60 x 16 f4 (L2-hot)

        #pragma unroll
        for (int r = 0; r < 4; r++) {
            if (r < rows) {
                bool isA = ((int)c_hseg[start + r] == hsA);
                const float4* dsm = isA ? dshA4 : dshB4;
                const float*  bs  = isA ? bshA  : bshB;
                const float4* xs4 = xb4 + r*(WW*16);

                // hoisted loads: 4 x (L2) + 4 d (LDS), all independent
                float4 a0 = xs4[(p0      )*16 + jq];
                float4 a1 = xs4[(p0 + 16)*16 + jq];
                float4 a2 = xs4[(p0 + 32)*16 + jq];
                float4 a3 = v3 ? xs4[p3*16 + jq] : make_float4(0.f,0.f,0.f,0.f);
                float4 d0 = dsm[ws0*16 + jq];
                float4 d1 = dsm[ws1*16 + jq];
                float4 d2 = dsm[ws2*16 + jq];
                float4 d3 = dsm[ws3*16 + jq];

                float t0 = a0.x*d0.x + a0.y*d0.y + a0.z*d0.z + a0.w*d0.w;
                float t1 = a1.x*d1.x + a1.y*d1.y + a1.z*d1.z + a1.w*d1.w;
                float t2 = a2.x*d2.x + a2.y*d2.y + a2.z*d2.z + a2.w*d2.w;
                float t3 = a3.x*d3.x + a3.y*d3.y + a3.z*d3.z + a3.w*d3.w;

                // 4 independent shfl trees, interleaved (4-way ILP)
                #pragma unroll
                for (int o = 1; o < 16; o <<= 1) {
                    t0 += __shfl_xor_sync(0xffffffffu, t0, o);
                    t1 += __shfl_xor_sync(0xffffffffu, t1, o);
                    t2 += __shfl_xor_sync(0xffffffffu, t2, o);
                    t3 += __shfl_xor_sync(0xffffffffu, t3, o);
                }
                if (jq == 0) {
                    ashp[r*WW + p0]      = 0.125f*t0 + bs[ws0];
                    ashp[r*WW + p0 + 16] = 0.125f*t1 + bs[ws1];
                    ashp[r*WW + p0 + 32] = 0.125f*t2 + bs[ws2];
                    if (v3) ashp[r*WW + p3] = 0.125f*t3 + bs[ws3];
                }
            }
        }
        __syncthreads();

        if (tid < rows*WW) {
            float attn = ashp[tid];
            // log(sig+eps) - log(1-sig+eps) == attn  (|attn| small; err ~1e-6)
            float nx = -logf(-logf(nxv + 1e-8f) + 1e-8f);
            float nr = -logf(-logf(nrv + 1e-8f) + 1e-8f);
            const float invT = 1.f / (0.03f + 1e-8f);
            float l = (attn + nx - nr) * invT;
            out[gi0 + tid] = 1.f / (1.f + expf(-l));
        }
    }
}

// ---------------- launcher ----------------
extern "C" void kernel_launch(void* const* d_in, const int* in_sizes, int n_in,
                              void* d_out, int out_size) {
    const float* x       = (const float*)d_in[0];   // (64,30,60,64)
    const float* qk_w    = (const float*)d_in[1];   // (128,64)
    const float* qk_b    = (const float*)d_in[2];   // (128,)
    const float* score_w = (const float*)d_in[3];   // (1,3)
    const float* score_b = (const float*)d_in[4];   // (1,)
    const float* noise_x = (const float*)d_in[5];   // (64,1800,1)
    const float* noise_r = (const float*)d_in[6];   // (64,1800,1)
    float* out = (float*)d_out;                     // (64,1800,1)

    k_fused<<<NB*8, 256>>>(x, qk_w, qk_b, score_w, score_b,
                           noise_x, noise_r, out);
}

// round 17
// speedup vs baseline: 1.0714x; 1.0714x over previous
#include <cuda_runtime.h>
#include <math.h>

#define NB 64
#define HH 30
#define WW 60
#define DD 64
#define ROWB (WW*DD*4)      // 15360 bytes per (b,h) image row

// ---------------- scratch (device globals; no allocation) ----------------
__device__ float g_part[NB*16*16*DD];     // balanced partial cell sums (4 MB)
__device__ float g_dvec[NB*8*16*DD];      // dvec per (batch,hseg,combo) (2 MB)
__device__ float g_s[NB*128];             // raw s
__device__ unsigned g_cntA[NB*32];        // barrier counters (monotonic, replay-safe)
__device__ unsigned g_cntB[NB*32];

// ---------------- geometry LUTs ----------------
__constant__ int c_wstart[16] = {0,6,10,12,15,18,20,24,30,36,40,42,45,48,50,54};
__constant__ int c_wlen[16]   = {6,4,2,3,3,2,4,6, 6,4,2,3,3,2,4,6};
__constant__ unsigned char c_hseg[30] = {
  0,0,0,0,0,0, 1,1,1,1, 2,2, 3,3,3, 4,4,4, 5,5, 6,6,6,6, 7,7,7,7,7,7};
__constant__ unsigned char c_wseg[60] = {
  0,0,0,0,0,0, 1,1,1,1, 2,2, 3,3,3, 4,4,4, 5,5, 6,6,6,6, 7,7,7,7,7,7,
  8,8,8,8,8,8, 9,9,9,9, 10,10, 11,11,11, 12,12,12, 13,13, 14,14,14,14,
  15,15,15,15,15,15};
__constant__ unsigned char c_rh0[8]  = {0,1,1,2,2,3,3,4};
__constant__ unsigned char c_rh1[8]  = {0,0,1,1,1,1,2,2};
__constant__ unsigned char c_rh2[8]  = {0,0,0,0,1,1,1,1};
__constant__ unsigned char c_rw0[16] = {0,1,1,2,2,3,3,4,5,6,6,7,7,8,8,9};
__constant__ unsigned char c_rw1[16] = {0,0,1,1,1,1,2,2,3,3,4,4,4,4,5,5};
__constant__ unsigned char c_rw2[16] = {0,0,0,0,1,1,1,1,2,2,2,2,3,3,3,3};
__constant__ unsigned char p0_hf[5]={0,1,3,5,7},              p0_hc[5]={1,2,2,2,1};
__constant__ unsigned char p0_wf[10]={0,1,3,5,7,8,9,11,13,15},p0_wc[10]={1,2,2,2,1,1,2,2,2,1};
__constant__ unsigned char p1_hf[3]={0,2,6},                  p1_hc[3]={2,4,2};
__constant__ unsigned char p1_wf[6]={0,2,6,8,10,14},          p1_wc[6]={2,4,2,2,4,2};
__constant__ unsigned char p2_hf[2]={0,4},                    p2_hc[2]={4,4};
__constant__ unsigned char p2_wf[4]={0,4,8,12},               p2_wc[4]={4,4,4,4};
// hseg -> two g_part slots summing to its cells (slots 1,9,15 are zeros)
__constant__ unsigned char c_i1[8] = {0,3,5,7,8,10,11,13};
__constant__ unsigned char c_i2[8] = {2,4,6,1,9,15,12,14};

// ---------------- async / barrier helpers ----------------
__device__ __forceinline__ unsigned s2u(const void* p) {
    unsigned a;
    asm("{ .reg .u64 t; cvta.to.shared.u64 t, %1; cvt.u32.u64 %0, t; }"
        : "=r"(a) : "l"(p));
    return a;
}
__device__ __forceinline__ void mbar_init(unsigned m, unsigned cnt) {
    asm volatile("mbarrier.init.shared.b64 [%0], %1;" :: "r"(m), "r"(cnt) : "memory");
}
__device__ __forceinline__ void mbar_expect(unsigned m, unsigned bytes) {
    asm volatile("mbarrier.arrive.expect_tx.shared.b64 _, [%0], %1;"
                 :: "r"(m), "r"(bytes) : "memory");
}
__device__ __forceinline__ void bulk_g2s(unsigned dst, const void* src,
                                         unsigned bytes, unsigned m) {
    asm volatile(
        "cp.async.bulk.shared::cluster.global.mbarrier::complete_tx::bytes "
        "[%0], [%1], %2, [%3];"
        :: "r"(dst), "l"(src), "r"(bytes), "r"(m) : "memory");
}
__device__ __forceinline__ void mbar_wait(unsigned m, unsigned parity) {
    asm volatile(
        "{\n\t.reg .pred P;\n\t"
        "WL_%=:\n\t"
        "mbarrier.try_wait.parity.acquire.cta.shared::cta.b64 P, [%0], %1;\n\t"
        "@P bra WD_%=;\n\t"
        "bra WL_%=;\n\t"
        "WD_%=:\n\t}"
        :: "r"(m), "r"(parity) : "memory");
}
__device__ __forceinline__ void fence_async() {
    asm volatile("fence.proxy.async.shared::cta;" ::: "memory");
}
__device__ __forceinline__ void batch_barrier(unsigned* cnt, int tid) {
    __threadfence();                         // release this block's stores
    __syncthreads();
    if (tid == 0) {
        unsigned o = atomicAdd(cnt, 1u);
        unsigned target = ((o >> 3) + 1u) << 3;   // next multiple of 8
        while ((int)(*(volatile unsigned*)cnt - target) < 0) { }   // pure spin: min wake latency
        __threadfence();                     // acquire
    }
    __syncthreads();
}

// ============ fused kernel: grid = 512 = (batch, k), one wave ============
__global__ __launch_bounds__(256, 4) void k_fused(
    const float* __restrict__ x,
    const float* __restrict__ qk_w,
    const float* __restrict__ qk_b,
    const float* __restrict__ score_w,
    const float* __restrict__ score_b,
    const float* __restrict__ noise_x,
    const float* __restrict__ noise_r,
    float* __restrict__ out)
{
    // arena layout (byte offsets):
    //  A: slabs 0/1/2 at 0/15360/30720                        (46080)
    //  B: cells @0 (32768), rs4 @32768 (5120), ush4 @37888 (4096),
    //     tsm @41984 (4096); then Msh @0 (Wk^T pad-65 16640 / Wq 16384)
    //  C: dshA @0, dshB @4096, ash @8192, bshA/B @9216
    __shared__ __align__(128) unsigned char arena[46080];
    __shared__ __align__(8) unsigned long long mbar[3];
    __shared__ float qkb[128];

    int bi  = blockIdx.x;
    int b   = bi >> 3, k = bi & 7;
    int tid = threadIdx.x;
    int start = (k*30) >> 3, end = ((k+1)*30) >> 3;   // sizes 3,4,4,4,3,4,4,4
    int rows  = end - start;
    int hsA = c_hseg[start], hsB = c_hseg[end - 1];   // range spans <= 2 hsegs

    unsigned mb = s2u(mbar);
    if (tid == 0)
        for (int i = 0; i < 3; i++) mbar_init(mb + i*8, 1);
    if (tid < 128) qkb[tid] = qk_b[tid];
    float w0 = score_w[0], w1 = score_w[1], w2 = score_w[2];
    float sb = score_b[0];
    // noise preload (input-only): overlaps all phases
    int gi0 = (b*HH + start)*WW;
    float nxv = 0.f, nrv = 0.f;
    if (tid < rows*WW) { nxv = noise_x[gi0 + tid]; nrv = noise_r[gi0 + tid]; }
    __syncthreads();

    const char* xrow = (const char*)x + (size_t)(b*HH + start) * ROWB;

    // ---------------- phase A: balanced TMA cell partials -------------------
    {
        if (tid == 0) {
            int pre = rows < 3 ? rows : 3;
            for (int r = 0; r < pre; r++) {
                mbar_expect(mb + r*8, ROWB);
                bulk_g2s(s2u(arena + r*15360), xrow + (size_t)r*ROWB, ROWB, mb + r*8);
            }
        }
        int ws = tid >> 4, j = tid & 15;
        int a0i = c_wstart[ws], l0 = c_wlen[ws];
        float4 accA = make_float4(0.f,0.f,0.f,0.f);
        float4 accB = make_float4(0.f,0.f,0.f,0.f);
        #pragma unroll
        for (int r = 0; r < 4; r++) {
            if (r < rows) {
                int s = r % 3;
                mbar_wait(mb + s*8, r/3);
                const float4* sl = (const float4*)(arena + s*15360) + a0i*16 + j;
                float4 t = make_float4(0.f,0.f,0.f,0.f);
                #pragma unroll
                for (int w = 0; w < 6; w++) {
                    if (w < l0) {
                        float4 v = sl[w*16];
                        t.x += v.x; t.y += v.y; t.z += v.z; t.w += v.w;
                    }
                }
                if ((int)c_hseg[start + r] == hsA) {
                    accA.x += t.x; accA.y += t.y; accA.z += t.z; accA.w += t.w;
                } else {
                    accB.x += t.x; accB.y += t.y; accB.z += t.z; accB.w += t.w;
                }
                if (r + 3 < rows) {          // only rows=4, r=0: re-arm slab 0
                    __syncthreads();
                    if (tid == 0) {
                        fence_async();
                        mbar_expect(mb + s*8, ROWB);
                        bulk_g2s(s2u(arena + s*15360), xrow + (size_t)(r+3)*ROWB,
                                 ROWB, mb + s*8);
                    }
                }
            }
        }
        float4* pp = (float4*)(g_part + ((size_t)b*16 + k*2) * 1024);
        pp[ws*16 + j]       = accA;          // slot k*2
        pp[256 + ws*16 + j] = accB;          // slot k*2+1 (zeros if single-hseg)
    }

    batch_barrier(&g_cntA[b*32], tid);

    // ---------------- phase B: dense cell merge -> smem regions -> dvec -----
    {
        float4* cells4 = (float4*)arena;                 // 8 hsegs x 256 f4
        float4* rs4    = (float4*)(arena + 32768);       // 20 regions x 16 f4
        float4* ush4   = (float4*)(arena + 37888);       // 16 combos x 16 f4
        float*  tsm    = (float*)(arena + 41984);        // 16 x 64
        float*  Msh    = (float*)arena;                  // over dead cells later

        // 1) dense cooperative merge of partial slots (independent L2 loads)
        const float4* pb4 = (const float4*)(g_part + (size_t)b * 16384);
        #pragma unroll
        for (int it = 0; it < 8; it++) {
            int v = tid + it*256;                        // 0..2047
            int hs2 = v >> 8, o = v & 255;
            float4 v1 = pb4[(int)c_i1[hs2]*256 + o];
            float4 v2 = pb4[(int)c_i2[hs2]*256 + o];
            cells4[v] = make_float4(v1.x+v2.x, v1.y+v2.y, v1.z+v2.z, v1.w+v2.w);
        }
        __syncthreads();

        // 2) region sums from smem (LDS gather, short chains)
        int rh0 = c_rh0[k], rh1 = c_rh1[k], rh2 = c_rh2[k];
        for (int v = tid; v < 320; v += 256) {
            int jj = v >> 4, dq = v & 15;
            int hf, hc, wf, wc;
            if (jj < 10)      { hf=p0_hf[rh0]; hc=p0_hc[rh0]; wf=p0_wf[jj];   wc=p0_wc[jj]; }
            else if (jj < 16) { int rw=jj-10; hf=p1_hf[rh1]; hc=p1_hc[rh1]; wf=p1_wf[rw]; wc=p1_wc[rw]; }
            else              { int rw=jj-16; hf=p2_hf[rh2]; hc=p2_hc[rh2]; wf=p2_wf[rw]; wc=p2_wc[rw]; }
            float4 s = make_float4(0.f,0.f,0.f,0.f);
            for (int a = 0; a < hc; a++) {
                const float4* cr = cells4 + ((hf + a)*16 + wf)*16 + dq;
                for (int c2 = 0; c2 < wc; c2++) {
                    float4 v1 = cr[c2*16];
                    s.x += v1.x; s.y += v1.y; s.z += v1.z; s.w += v1.w;
                }
            }
            rs4[v] = s;
        }
        __syncthreads();

        float aw0 = w0*(1.f/36.f), aw1 = w1*(1.f/100.f), aw2 = w2*(1.f/225.f);
        float wsum = w0 + w1 + w2;

        // 3) u[combo] (256 threads = 16 combos x 16 quads)
        {
            int wsg = tid >> 4, dq = tid & 15;
            float4 r0 = rs4[(int)c_rw0[wsg]*16 + dq];
            float4 r1 = rs4[(10 + (int)c_rw1[wsg])*16 + dq];
            float4 r2 = rs4[(16 + (int)c_rw2[wsg])*16 + dq];
            float4 u;
            u.x = aw0*r0.x + aw1*r1.x + aw2*r2.x;
            u.y = aw0*r0.y + aw1*r1.y + aw2*r2.y;
            u.z = aw0*r0.z + aw1*r1.z + aw2*r2.z;
            u.w = aw0*r0.w + aw1*r1.w + aw2*r2.w;
            ush4[tid] = u;
        }
        __syncthreads();                     // cells dead; Msh may overwrite

        // 4) Wk transposed, pad-65 (conflict-free)
        for (int v = tid; v < 4096; v += 256) {
            int ee = v >> 6, d = v & 63;
            Msh[d*65 + ee] = qk_w[4096 + v];
        }
        __syncthreads();

        // 5) t[c] = Wk u[c] + wsum*bk   (thread = (e, 4-combo group))
        int e = tid & 63, cg = tid >> 6;
        {
            float init = wsum * qkb[64 + e];
            float t0 = init, t1 = init, t2 = init, t3 = init;
            #pragma unroll
            for (int fq = 0; fq < 16; fq++) {
                int d = fq*4;
                float m0 = Msh[(d+0)*65 + e];
                float m1 = Msh[(d+1)*65 + e];
                float m2 = Msh[(d+2)*65 + e];
                float m3 = Msh[(d+3)*65 + e];
                float4 ua = ush4[(cg*4 + 0)*16 + fq];
                float4 ub = ush4[(cg*4 + 1)*16 + fq];
                float4 uc = ush4[(cg*4 + 2)*16 + fq];
                float4 ud = ush4[(cg*4 + 3)*16 + fq];
                t0 += m0*ua.x + m1*ua.y + m2*ua.z + m3*ua.w;
                t1 += m0*ub.x + m1*ub.y + m2*ub.z + m3*ub.w;
                t2 += m0*uc.x + m1*uc.y + m2*uc.z + m3*uc.w;
                t3 += m0*ud.x + m1*ud.y + m2*ud.z + m3*ud.w;
            }
            tsm[(cg*4 + 0)*64 + e] = t0;
            tsm[(cg*4 + 1)*64 + e] = t1;
            tsm[(cg*4 + 2)*64 + e] = t2;
            tsm[(cg*4 + 3)*64 + e] = t3;
        }
        __syncthreads();

        // 6) reload Msh with Wq (straight layout)
        for (int v = tid; v < 4096; v += 256) Msh[v] = qk_w[v];
        __syncthreads();

        // 7) s[c] = bq . t[c]
        int lane = tid & 31, warp = tid >> 5;
        for (int c = warp; c < 16; c += 8) {
            float sv = tsm[c*64 + lane]      * qkb[lane]
                     + tsm[c*64 + 32 + lane] * qkb[32 + lane];
            #pragma unroll
            for (int o = 16; o; o >>= 1) sv += __shfl_xor_sync(0xffffffffu, sv, o);
            if (lane == 0) g_s[b*128 + k*16 + c] = sv;
        }

        // 8) dvec[c] = Wq^T t[c] -> global
        {
            int jj = tid & 63;
            float d0 = 0.f, d1 = 0.f, d2 = 0.f, d3 = 0.f;
            const float4* t0p = (const float4*)(tsm + (cg*4 + 0)*64);
            const float4* t1p = (const float4*)(tsm + (cg*4 + 1)*64);
            const float4* t2p = (const float4*)(tsm + (cg*4 + 2)*64);
            const float4* t3p = (const float4*)(tsm + (cg*4 + 3)*64);
            #pragma unroll
            for (int eq = 0; eq < 16; eq++) {
                int ee = eq*4;
                float a0v = Msh[(ee+0)*64 + jj];
                float a1v = Msh[(ee+1)*64 + jj];
                float a2v = Msh[(ee+2)*64 + jj];
                float a3v = Msh[(ee+3)*64 + jj];
                float4 ta = t0p[eq], tb = t1p[eq], tc = t2p[eq], td = t3p[eq];
                d0 += a0v*ta.x + a1v*ta.y + a2v*ta.z + a3v*ta.w;
                d1 += a0v*tb.x + a1v*tb.y + a2v*tb.z + a3v*tb.w;
                d2 += a0v*tc.x + a1v*tc.y + a2v*tc.z + a3v*tc.w;
                d3 += a0v*td.x + a1v*td.y + a2v*td.z + a3v*td.w;
            }
            float* dst = g_dvec + ((size_t)(b*8 + k)*16 + cg*4)*64;
            dst[0*64 + jj] = d0;
            dst[1*64 + jj] = d1;
            dst[2*64 + jj] = d2;
            dst[3*64 + jj] = d3;
        }
    }

    batch_barrier(&g_cntB[b*32], tid);

    // ---------------- phase C: direct-L2 dot + gumbel, sync-free rows -------
    {
        float4* dshA4 = (float4*)arena;
        float4* dshB4 = (float4*)(arena + 4096);
        float*  ashp  = (float*)(arena + 8192);          // rows*60 <= 240
        float*  bshA  = (float*)(arena + 9216);
        float*  bshB  = bshA + 16;

        const float4* srcA = (const float4*)(g_dvec + (size_t)(b*8 + hsA)*1024);
        const float4* srcB = (const float4*)(g_dvec + (size_t)(b*8 + hsB)*1024);
        dshA4[tid] = srcA[tid];              // 256 f4 = full 16x64 each
        dshB4[tid] = srcB[tid];
        if (tid < 16) {
            bshA[tid] = 0.125f * g_s[b*128 + hsA*16 + tid] + sb;
            bshB[tid] = 0.125f * g_s[b*128 + hsB*16 + tid] + sb;
        }
        __syncthreads();

        int lane = tid & 31, warp = tid >> 5;
        int half = lane >> 4, jq = lane & 15;
        int p0 = warp*2 + half;              // 0..15
        const float4* xb4 = (const float4*)xrow;   // rows x 60 x 16 f4 (L2-hot)

        #pragma unroll
        for (int r = 0; r < 4; r++) {
            if (r < rows) {
                bool isA = ((int)c_hseg[start + r] == hsA);
                const float4* dsm = isA ? dshA4 : dshB4;
                const float*  bs  = isA ? bshA  : bshB;
                const float4* xs4 = xb4 + r*(WW*16);
                #pragma unroll
                for (int it = 0; it < 4; it++) {
                    int p = p0 + it*16;
                    float dot = 0.f; int wsg = 0;
                    if (p < WW) {
                        wsg = c_wseg[p];
                        float4 a = xs4[p*16 + jq];       // 256B/half-warp coalesced
                        float4 d = dsm[wsg*16 + jq];
                        dot = a.x*d.x + a.y*d.y + a.z*d.z + a.w*d.w;
                    }
                    #pragma unroll
                    for (int o = 1; o < 16; o <<= 1)
                        dot += __shfl_xor_sync(0xffffffffu, dot, o);
                    if (p < WW && jq == 0) ashp[r*WW + p] = 0.125f*dot + bs[wsg];
                }
            }
        }
        __syncthreads();

        if (tid < rows*WW) {
            float attn = ashp[tid];
            // log(sig+eps) - log(1-sig+eps) == attn  (|attn| small; err ~1e-6)
            float nx = -logf(-logf(nxv + 1e-8f) + 1e-8f);
            float nr = -logf(-logf(nrv + 1e-8f) + 1e-8f);
            const float invT = 1.f / (0.03f + 1e-8f);
            float l = (attn + nx - nr) * invT;
            out[gi0 + tid] = 1.f / (1.f + expf(-l));
        }
    }
}

// ---------------- launcher ----------------
extern "C" void kernel_launch(void* const* d_in, const int* in_sizes, int n_in,
                              void* d_out, int out_size) {
    const float* x       = (const float*)d_in[0];   // (64,30,60,64)
    const float* qk_w    = (const float*)d_in[1];   // (128,64)
    const float* qk_b    = (const float*)d_in[2];   // (128,)
    const float* score_w = (const float*)d_in[3];   // (1,3)
    const float* score_b = (const float*)d_in[4];   // (1,)
    const float* noise_x = (const float*)d_in[5];   // (64,1800,1)
    const float* noise_r = (const float*)d_in[6];   // (64,1800,1)
    float* out = (float*)d_out;                     // (64,1800,1)

    k_fused<<<NB*8, 256>>>(x, qk_w, qk_b, score_w, score_b,
                           noise_x, noise_r, out);
}